// round 10
// baseline (speedup 1.0000x reference)
#include <cuda_runtime.h>
#include <cuda_bf16.h>
#include <cuda_fp16.h>
#include <cstdint>
#include <math.h>

// ---------------- problem constants ----------------
#define TSTEPS 32
#define NBATCH 64
#define NPIX   64
#define ENCC   1536
#define EMBD   512
#define ADIM   512
#define HDIM   512
#define G4     2048     // 4*H
#define VOCAB  10000
#define VPAD   10048    // 157*64
#define MROWS  4096     // N*P
#define KINIT  98304    // P*ENC
#define NSPLIT 96       // init split-K
#define PGRID  148      // persistent loop grid (1 CTA/SM guaranteed)

// ---------------- scratch (__device__ globals; no allocation) ----------------
__device__ __align__(16) __nv_bfloat16 d_feat_h[MROWS * ENCC];
__device__ __align__(16) __nv_bfloat16 d_feat_l[MROWS * ENCC];
__device__ __align__(16) __nv_bfloat16 d_Wih_h[G4 * G4];
__device__ __align__(16) __nv_bfloat16 d_Wih_l[G4 * G4];
__device__ __align__(16) __nv_bfloat16 d_afW_h[ADIM * ENCC];
__device__ __align__(16) __nv_bfloat16 d_afW_l[ADIM * ENCC];
__device__ __align__(16) __nv_bfloat16 d_fcW_h[VPAD * HDIM];
__device__ __align__(16) __nv_bfloat16 d_fcW_l[VPAD * HDIM];
__device__ __align__(16) __nv_bfloat16 d_embbf_h[TSTEPS * NBATCH * EMBD];
__device__ __align__(16) __nv_bfloat16 d_embbf_l[TSTEPS * NBATCH * EMBD];
__device__ __align__(16) __nv_bfloat16 d_houtbf_h[TSTEPS * NBATCH * HDIM];
__device__ __align__(16) __nv_bfloat16 d_houtbf_l[TSTEPS * NBATCH * HDIM];

__device__ __align__(16) __half d_attn_img[MROWS * ADIM];            // fp16, 4 MB
__device__ __align__(16) __half d_G[(size_t)NBATCH * G4 * NPIX];     // fp16, 16.7 MB
__device__ float d_pre[TSTEPS * NBATCH * G4];
__device__ float d_part[NSPLIT * 64 * 1024];       // init split-K partials (25MB)
__device__ float d_h[NBATCH * HDIM];
__device__ float d_c[NBATCH * HDIM];
__device__ float d_P1[4 * NBATCH * ADIM];
__device__ float d_P3[4 * NBATCH * G4];
__device__ float d_logits[NBATCH * NPIX];

// global barrier state for the persistent loop kernel
__device__ unsigned int g_count;
__device__ unsigned int g_phase;

// =====================================================================
// warp-MMA + cp.async helpers (sm_80+ PTX, no arch-feature gating)
// =====================================================================
__device__ __forceinline__ uint32_t smem_u32(const void* p) {
    uint32_t a;
    asm("{ .reg .u64 t; cvta.to.shared.u64 t, %1; cvt.u32.u64 %0, t; }" : "=r"(a) : "l"(p));
    return a;
}
__device__ __forceinline__ void ldsm_x4(uint32_t* r, uint32_t addr) {
    asm volatile("ldmatrix.sync.aligned.m8n8.x4.shared.b16 {%0,%1,%2,%3}, [%4];"
                 : "=r"(r[0]), "=r"(r[1]), "=r"(r[2]), "=r"(r[3]) : "r"(addr));
}
__device__ __forceinline__ void ldsm_x4_t(uint32_t* r, uint32_t addr) {
    asm volatile("ldmatrix.sync.aligned.m8n8.x4.trans.shared.b16 {%0,%1,%2,%3}, [%4];"
                 : "=r"(r[0]), "=r"(r[1]), "=r"(r[2]), "=r"(r[3]) : "r"(addr));
}
__device__ __forceinline__ void mma_bf16(float* c, const uint32_t* a, const uint32_t* b) {
    asm volatile(
        "mma.sync.aligned.m16n8k16.row.col.f32.bf16.bf16.f32 "
        "{%0,%1,%2,%3}, {%4,%5,%6,%7}, {%8,%9}, {%0,%1,%2,%3};"
        : "+f"(c[0]), "+f"(c[1]), "+f"(c[2]), "+f"(c[3])
        : "r"(a[0]), "r"(a[1]), "r"(a[2]), "r"(a[3]), "r"(b[0]), "r"(b[1]));
}
__device__ __forceinline__ void cp16(uint32_t dst, const void* src, bool pred) {
    int sz = pred ? 16 : 0;
    asm volatile("cp.async.cg.shared.global [%0], [%1], 16, %2;"
                 :: "r"(dst), "l"(src), "r"(sz) : "memory");
}
#define CP_COMMIT() asm volatile("cp.async.commit_group;" ::: "memory")
#define CP_WAIT1()  asm volatile("cp.async.wait_group 1;" ::: "memory")

// =====================================================================
// Fused fp32 -> bf16 hi/lo conversion for all 4 weight/feature arrays.
// =====================================================================
__global__ void cvt_all(const float* __restrict__ feat,
                        const float* __restrict__ Wih,
                        const float* __restrict__ afW,
                        const float* __restrict__ fcW)
{
    int b = blockIdx.x;
    const float* src;
    __nv_bfloat16 *dh, *dl;
    int n_src, lb;
    if (b < 6144)       { src = feat; dh = d_feat_h; dl = d_feat_l; n_src = MROWS * ENCC; lb = b; }
    else if (b < 10240) { src = Wih;  dh = d_Wih_h;  dl = d_Wih_l;  n_src = G4 * G4;      lb = b - 6144; }
    else if (b < 11008) { src = afW;  dh = d_afW_h;  dl = d_afW_l;  n_src = ADIM * ENCC;  lb = b - 10240; }
    else                { src = fcW;  dh = d_fcW_h;  dl = d_fcW_l;  n_src = VOCAB * HDIM; lb = b - 11008; }
    int i = (lb * 256 + threadIdx.x) * 4;
    float4 v = make_float4(0.f, 0.f, 0.f, 0.f);
    if (i < n_src) v = *(const float4*)&src[i];
    float a[4] = {v.x, v.y, v.z, v.w};
    __nv_bfloat16 h[4], l[4];
#pragma unroll
    for (int j = 0; j < 4; j++) {
        h[j] = __float2bfloat16(a[j]);
        l[j] = __float2bfloat16(a[j] - __bfloat162float(h[j]));
    }
    *(__nv_bfloat162*)&dh[i]     = __halves2bfloat162(h[0], h[1]);
    *(__nv_bfloat162*)&dh[i + 2] = __halves2bfloat162(h[2], h[3]);
    *(__nv_bfloat162*)&dl[i]     = __halves2bfloat162(l[0], l[1]);
    *(__nv_bfloat162*)&dl[i + 2] = __halves2bfloat162(l[2], l[3]);
}

// embedding gather straight into bf16 hi/lo [t*64+n][e]
__global__ void emb_gather_bf(const int* __restrict__ cap,
                              const float* __restrict__ EW,
                              __nv_bfloat16* __restrict__ dh,
                              __nv_bfloat16* __restrict__ dl)
{
    int m = blockIdx.x;                 // t*64+n
    int n = m & 63, t = m >> 6;
    int tok = cap[n * TSTEPS + t];
    int i = threadIdx.x * 4;            // 128 thr * 4 = 512
    float4 v = *(const float4*)&EW[(size_t)tok * EMBD + i];
    float a[4] = {v.x, v.y, v.z, v.w};
    __nv_bfloat16 h[4], l[4];
#pragma unroll
    for (int j = 0; j < 4; j++) {
        h[j] = __float2bfloat16(a[j]);
        l[j] = __float2bfloat16(a[j] - __bfloat162float(h[j]));
    }
    size_t o = (size_t)m * EMBD + i;
    *(__nv_bfloat162*)&dh[o]     = __halves2bfloat162(h[0], h[1]);
    *(__nv_bfloat162*)&dh[o + 2] = __halves2bfloat162(h[2], h[3]);
    *(__nv_bfloat162*)&dl[o]     = __halves2bfloat162(l[0], l[1]);
    *(__nv_bfloat162*)&dl[o + 2] = __halves2bfloat162(l[2], l[3]);
}

// =====================================================================
// Warp-MMA NT GEMM, bf16 hi/lo split, fp32 accumulate, cp.async 2-stage.
// mode 0: fp32 C[m*ldc+n] (+bias)
// mode 3: merged — blockIdx.x<8: attn_img fp16 (+bias); else G fp16 layout
// =====================================================================
#define ASTR 72
#define AH_OFF 0
#define AL_OFF 18432
#define BH_OFF 36864
#define BL_OFF 46080
#define STAGE_BYTES 55296
#define MMA_SMEM_BYTES (2 * STAGE_BYTES)

__global__ void __launch_bounds__(256) mma_nt(
    const __nv_bfloat16* __restrict__ Ah, const __nv_bfloat16* __restrict__ Al,
    int lda, int Mvalid,
    const __nv_bfloat16* __restrict__ Bh, const __nv_bfloat16* __restrict__ Bl,
    int ldb,
    float* __restrict__ C, int Nvalid, int ldc,
    int chunks, const float* __restrict__ bias, int mode)
{
    extern __shared__ char smem[];
    const uint32_t sb = smem_u32(smem);
    const int tid = threadIdx.x, lane = tid & 31, wid = tid >> 5;
    const int wm = wid >> 1, wn = wid & 1;
    const int m0 = blockIdx.y * 128;

    const __nv_bfloat16* bH = Bh;
    const __nv_bfloat16* bL = Bl;
    const float* bptr = bias;
    int n0 = blockIdx.x * 64;
    int mode_eff = mode;
    if (mode == 3) {
        if (blockIdx.x < 8) {
            mode_eff = 4;                       // attn_img fp16 store
        } else {
            bH = d_Wih_h; bL = d_Wih_l; ldb = G4;
            bptr = nullptr;
            n0 = (blockIdx.x - 8) * 64;
            mode_eff = 1;                       // G fp16 store
        }
    }

    float acc[2][4][4];
#pragma unroll
    for (int i = 0; i < 2; i++)
#pragma unroll
        for (int j = 0; j < 4; j++)
#pragma unroll
            for (int q = 0; q < 4; q++) acc[i][j][q] = 0.f;

    const uint32_t a_row = wm * 32 + (lane & 15);
    const uint32_t a_k   = ((lane >> 4) & 1) * 8;
    const uint32_t b_row = wn * 32 + (lane & 7) + ((lane >> 4) & 1) * 8;
    const uint32_t b_k   = ((lane >> 3) & 1) * 8;

    auto load_stage = [&](int ic, int st) {
        const uint32_t stb = sb + st * STAGE_BYTES;
        const long long kc = (long long)ic * 64;
#pragma unroll
        for (int it = 0; it < 4; it++) {              // A: 128 rows x 64k
            int idx = it * 256 + tid;
            int row = idx >> 3, k8 = (idx & 7) * 8;
            int m = m0 + row;
            bool p = (m < Mvalid);
            int mc = p ? m : (Mvalid - 1);
            uint32_t off = (row * ASTR + k8) * 2;
            cp16(stb + AH_OFF + off, &Ah[(size_t)mc * lda + kc + k8], p);
            cp16(stb + AL_OFF + off, &Al[(size_t)mc * lda + kc + k8], p);
        }
#pragma unroll
        for (int it = 0; it < 2; it++) {              // B: 64 rows x 64k
            int idx = it * 256 + tid;
            int row = idx >> 3, k8 = (idx & 7) * 8;
            uint32_t off = (row * ASTR + k8) * 2;
            cp16(stb + BH_OFF + off, &bH[(size_t)(n0 + row) * ldb + kc + k8], true);
            cp16(stb + BL_OFF + off, &bL[(size_t)(n0 + row) * ldb + kc + k8], true);
        }
    };

    load_stage(0, 0);
    CP_COMMIT();

    for (int ic = 0; ic < chunks; ic++) {
        const int s = ic & 1;
        if (ic + 1 < chunks) load_stage(ic + 1, s ^ 1);
        CP_COMMIT();
        CP_WAIT1();
        __syncthreads();

        const uint32_t stb = sb + s * STAGE_BYTES;
#pragma unroll
        for (int ks = 0; ks < 4; ks++) {
            const uint32_t k16 = ks * 16;
            uint32_t ahf[2][4], alf[2][4], bhf[2][4], blf[2][4];
#pragma unroll
            for (int mt = 0; mt < 2; mt++) {
                uint32_t off = ((a_row + mt * 16) * ASTR + k16 + a_k) * 2;
                ldsm_x4(ahf[mt], stb + AH_OFF + off);
                ldsm_x4(alf[mt], stb + AL_OFF + off);
            }
#pragma unroll
            for (int np = 0; np < 2; np++) {
                uint32_t off = ((b_row + np * 16) * ASTR + k16 + b_k) * 2;
                ldsm_x4(bhf[np], stb + BH_OFF + off);
                ldsm_x4(blf[np], stb + BL_OFF + off);
            }
#pragma unroll
            for (int mt = 0; mt < 2; mt++)
#pragma unroll
                for (int np = 0; np < 2; np++) {
                    mma_bf16(acc[mt][np * 2 + 0], ahf[mt], &bhf[np][0]);
                    mma_bf16(acc[mt][np * 2 + 1], ahf[mt], &bhf[np][2]);
                    mma_bf16(acc[mt][np * 2 + 0], ahf[mt], &blf[np][0]);
                    mma_bf16(acc[mt][np * 2 + 1], ahf[mt], &blf[np][2]);
                    mma_bf16(acc[mt][np * 2 + 0], alf[mt], &bhf[np][0]);
                    mma_bf16(acc[mt][np * 2 + 1], alf[mt], &bhf[np][2]);
                }
        }
        __syncthreads();
    }

    // ---- store ----
    const int g = lane >> 2, tg = lane & 3;
#pragma unroll
    for (int mt = 0; mt < 2; mt++) {
#pragma unroll
        for (int nt = 0; nt < 4; nt++) {
            int r0 = m0 + wm * 32 + mt * 16 + g;
            int c0 = n0 + wn * 32 + nt * 8 + tg * 2;
#pragma unroll
            for (int q = 0; q < 4; q++) {
                int m = r0 + (q >> 1) * 8;
                int n = c0 + (q & 1);
                if (m >= Mvalid) continue;
                float v = acc[mt][nt][q];
                if (mode_eff == 1) {
                    int nb = m >> 6, p = m & 63;
                    d_G[((size_t)nb * 2048 + n) * 64 + p] = __float2half(v);
                } else if (mode_eff == 4) {
                    d_attn_img[(size_t)m * ADIM + n] = __float2half(v + bptr[n]);
                } else {
                    if (n < Nvalid) {
                        if (bptr) v += bptr[n];
                        C[(size_t)m * ldc + n] = v;
                    }
                }
            }
        }
    }
}

// =====================================================================
// Fused init GEMM: h0|c0 = F(64x98304) @ [Wh|Wc]; split-K 96.
// =====================================================================
#define IBSTR 136
#define IA_H 0
#define IA_L 9216
#define IB_H 18432
#define IB_L 35840
#define INIT_SMEM_BYTES 53248

__global__ void __launch_bounds__(256) init_mma(
    const float* __restrict__ Wh, const float* __restrict__ Wc,
    float* __restrict__ P)
{
    extern __shared__ char smem[];
    const uint32_t sb = smem_u32(smem);
    __nv_bfloat16* Bsh = (__nv_bfloat16*)(smem + IB_H);
    __nv_bfloat16* Bsl = (__nv_bfloat16*)(smem + IB_L);
    const int tid = threadIdx.x, lane = tid & 31, wid = tid >> 5;
    const int wm = wid >> 2, wn = wid & 3;        // 2 x 4 warps, tile 64m x 128n
    const int bx = blockIdx.x;                    // 0-3 Wh, 4-7 Wc
    const float* __restrict__ W = (bx < 4) ? Wh : Wc;
    const int n0g = (bx & 3) * 128;
    const int outc0 = bx * 128;
    const size_t k0 = (size_t)blockIdx.y * 1024;

    float acc[2][4][4];
#pragma unroll
    for (int i = 0; i < 2; i++)
#pragma unroll
        for (int j = 0; j < 4; j++)
#pragma unroll
            for (int q = 0; q < 4; q++) acc[i][j][q] = 0.f;

    const uint32_t a_row = wm * 32 + (lane & 15);
    const uint32_t a_k   = ((lane >> 4) & 1) * 8;
    const uint32_t bt_k = ((lane >> 3) & 1) * 8 + (lane & 7);
    const uint32_t bt_n = ((lane >> 4) & 1) * 8;

    for (int ic = 0; ic < 16; ic++) {
        const size_t kg = k0 + ic * 64;
#pragma unroll
        for (int it = 0; it < 2; it++) {
            int idx = it * 256 + tid;
            int row = idx >> 3, k8 = (idx & 7) * 8;
            uint32_t off = (row * ASTR + k8) * 2;
            *(uint4*)(smem + IA_H + off) = *(const uint4*)&d_feat_h[(size_t)row * KINIT + kg + k8];
            *(uint4*)(smem + IA_L + off) = *(const uint4*)&d_feat_l[(size_t)row * KINIT + kg + k8];
        }
#pragma unroll
        for (int it = 0; it < 8; it++) {
            int idx = it * 256 + tid;
            int kk = idx >> 5, nn = (idx & 31) * 4;
            float4 v = *(const float4*)&W[(kg + kk) * 512 + n0g + nn];
            float a[4] = {v.x, v.y, v.z, v.w};
            __nv_bfloat16 h[4], l[4];
#pragma unroll
            for (int j = 0; j < 4; j++) {
                h[j] = __float2bfloat16(a[j]);
                l[j] = __float2bfloat16(a[j] - __bfloat162float(h[j]));
            }
            int o = kk * IBSTR + nn;
            *(__nv_bfloat162*)&Bsh[o]     = __halves2bfloat162(h[0], h[1]);
            *(__nv_bfloat162*)&Bsh[o + 2] = __halves2bfloat162(h[2], h[3]);
            *(__nv_bfloat162*)&Bsl[o]     = __halves2bfloat162(l[0], l[1]);
            *(__nv_bfloat162*)&Bsl[o + 2] = __halves2bfloat162(l[2], l[3]);
        }
        __syncthreads();

#pragma unroll
        for (int ks = 0; ks < 4; ks++) {
            const uint32_t k16 = ks * 16;
            uint32_t ahf[2][4], alf[2][4];
#pragma unroll
            for (int mt = 0; mt < 2; mt++) {
                uint32_t off = ((a_row + mt * 16) * ASTR + k16 + a_k) * 2;
                ldsm_x4(ahf[mt], sb + IA_H + off);
                ldsm_x4(alf[mt], sb + IA_L + off);
            }
#pragma unroll
            for (int ng = 0; ng < 2; ng++) {
                uint32_t bhf[4], blf[4];
                uint32_t off = ((k16 + bt_k) * IBSTR + wn * 32 + ng * 16 + bt_n) * 2;
                ldsm_x4_t(bhf, sb + IB_H + off);
                ldsm_x4_t(blf, sb + IB_L + off);
#pragma unroll
                for (int mt = 0; mt < 2; mt++) {
                    mma_bf16(acc[mt][ng * 2 + 0], ahf[mt], &bhf[0]);
                    mma_bf16(acc[mt][ng * 2 + 1], ahf[mt], &bhf[2]);
                    mma_bf16(acc[mt][ng * 2 + 0], ahf[mt], &blf[0]);
                    mma_bf16(acc[mt][ng * 2 + 1], ahf[mt], &blf[2]);
                    mma_bf16(acc[mt][ng * 2 + 0], alf[mt], &bhf[0]);
                    mma_bf16(acc[mt][ng * 2 + 1], alf[mt], &bhf[2]);
                }
            }
        }
        __syncthreads();
    }

    const int g = lane >> 2, tg = lane & 3;
    const int zb = blockIdx.y * 64;
#pragma unroll
    for (int mt = 0; mt < 2; mt++)
#pragma unroll
        for (int nt = 0; nt < 4; nt++) {
            int r0 = wm * 32 + mt * 16 + g;
            int c0 = outc0 + wn * 32 + nt * 8 + tg * 2;
#pragma unroll
            for (int q = 0; q < 4; q++) {
                int m = r0 + (q >> 1) * 8;
                int n = c0 + (q & 1);
                P[(size_t)(zb + m) * 1024 + n] = acc[mt][nt][q];
            }
        }
}

// deterministic reduce of NSPLIT split-K partials -> h0, c0
__global__ void reduce_init(const float* __restrict__ P,
                            float* __restrict__ h, float* __restrict__ c)
{
    int r = blockIdx.x * 256 + threadIdx.x;   // 65536
    float s = 0.f;
#pragma unroll
    for (int j = 0; j < NSPLIT; j++) s += P[(size_t)j * 65536 + r];
    int m = r >> 10, col = r & 1023;
    if (col < 512) h[m * 512 + col] = s;
    else           c[m * 512 + col - 512] = s;
}

// =====================================================================
// PERSISTENT LOOP KERNEL: all 32 recurrence steps in one launch.
// grid 148 x 512 threads (1 CTA/SM guaranteed). Global generation barrier.
// Phase A: P1/P3 partial GEMMs (160 units; CTAs 0-11 take 2).
// Phase B: softmax (CTAs 0-63). Phase C: gates+LSTM (CTAs 0-127).
// Cross-phase global data read via __ldcg (L1 is not coherent).
// Math is bitwise-identical to the R9 separate kernels.
// =====================================================================
__global__ void reset_bar() { g_count = 0u; g_phase = 0u; }

#define LOOP_SMEM 67584   // As[64][132] + Bs[64][132] floats

__global__ void __launch_bounds__(512) loop_persistent(
    const float* __restrict__ tokW,   // attn_token_W
    const float* __restrict__ Whh,
    const float* __restrict__ tb,     // attn_token_b
    const float* __restrict__ wfull,  // attn_full_W
    const float* __restrict__ b_ih,
    const float* __restrict__ b_hh)
{
    extern __shared__ char sm[];
    float* As = (float*)sm;                 // [64][132]
    float* Bs = (float*)(sm + 33792);       // [64][132]
    // phase-B overlay
    float* ah = (float*)sm;                 // 512
    float* wfs = ah + 512;                  // 512
    float* scs = wfs + 512;                 // 64
    // phase-C overlay
    float* lgs = (float*)sm;                // 64
    float* sg  = lgs + 64;                  // [4][256]

    const int tid = threadIdx.x;
    const unsigned cta = blockIdx.x;
    unsigned gen = 0;

    auto gbar = [&]() {
        gen++;
        __threadfence();
        __syncthreads();
        if (tid == 0) {
            unsigned a = atomicAdd(&g_count, 1u) + 1u;
            if (a == gen * (unsigned)PGRID) {
                atomicExch(&g_phase, gen);
            } else {
                volatile unsigned* pp = &g_phase;
                while (*pp < gen) { }
            }
        }
        __syncthreads();
    };

    for (int t = 0; t < TSTEPS; t++) {
        const float* pre_t = d_pre + (size_t)t * NBATCH * G4;

        // ---------------- phase A: P1/P3 partial GEMMs ----------------
        for (unsigned u = cta; u < 160u; u += PGRID) {
            int cb = u >> 2, ks = u & 3;
            const float* __restrict__ B;
            float* __restrict__ P;
            int Ncols;
            if (cb < 8) { B = tokW; P = d_P1; Ncols = 512; }
            else        { B = Whh;  P = d_P3; Ncols = 2048; cb -= 8; }
            const int k0 = ks * 128;
#pragma unroll
            for (int jj = 0; jj < 4; jj++) {        // A = h: 64 rows x 128k
                int q = tid + 512 * jj;
                int row = q >> 5, k4 = (q & 31) << 2;
                float4 v = __ldcg((const float4*)&d_h[row * 512 + k0 + k4]);
                *(float4*)&As[row * 132 + k4] = v;
            }
#pragma unroll
            for (int jj = 0; jj < 4; jj++) {        // B: 64 rows x 128k
                int q = tid + 512 * jj;
                int row = q >> 5, k4 = (q & 31) << 2;
                float4 v = *(const float4*)&B[(size_t)(cb * 64 + row) * 512 + k0 + k4];
                *(float4*)&Bs[row * 132 + k4] = v;
            }
            __syncthreads();
            const int cx = tid & 15, ry = tid >> 4;
            const int r0 = ry * 2;
            float a0c[4] = {0.f, 0.f, 0.f, 0.f};
            float a1c[4] = {0.f, 0.f, 0.f, 0.f};
#pragma unroll 4
            for (int k = 0; k < 128; k++) {
                float a0 = As[r0 * 132 + k], a1 = As[(r0 + 1) * 132 + k];
#pragma unroll
                for (int i = 0; i < 4; i++) {
                    float b = Bs[(cx + 16 * i) * 132 + k];
                    a0c[i] += a0 * b;
                    a1c[i] += a1 * b;
                }
            }
#pragma unroll
            for (int i = 0; i < 4; i++) {
                P[(size_t)(ks * 64 + r0) * Ncols + cb * 64 + cx + 16 * i]     = a0c[i];
                P[(size_t)(ks * 64 + r0 + 1) * Ncols + cb * 64 + cx + 16 * i] = a1c[i];
            }
            __syncthreads();
        }
        gbar();

        // ---------------- phase B: attn_h reduce + scores + softmax ----------------
        if (cta < 64) {
            const int n = cta;
            float v = tb[tid];
#pragma unroll
            for (int s = 0; s < 4; s++)
                v += __ldcg(&d_P1[(size_t)(s * 64 + n) * 512 + tid]);
            ah[tid] = v;
            wfs[tid] = wfull[tid];
            __syncthreads();

            const int warp = tid >> 5, lane = tid & 31;
            for (int p = warp; p < 64; p += 16) {
                const __half* img = &d_attn_img[(size_t)(n * 64 + p) * 512];
                float s = 0.f;
#pragma unroll
                for (int a = lane; a < 512; a += 32) {
                    float e = ah[a] + __half2float(img[a]);
                    if (e > 0.f) s += e * wfs[a];
                }
#pragma unroll
                for (int o = 16; o > 0; o >>= 1) s += __shfl_xor_sync(0xFFFFFFFFu, s, o);
                if (lane == 0) scs[p] = s;
            }
            __syncthreads();
            if (tid < 32) {
                float s0 = scs[tid], s1 = scs[tid + 32];
                float mx = fmaxf(s0, s1);
#pragma unroll
                for (int o = 16; o > 0; o >>= 1) mx = fmaxf(mx, __shfl_xor_sync(0xFFFFFFFFu, mx, o));
                float e0 = expf(s0 - mx), e1 = expf(s1 - mx);
                float sum = e0 + e1;
#pragma unroll
                for (int o = 16; o > 0; o >>= 1) sum += __shfl_xor_sync(0xFFFFFFFFu, sum, o);
                float inv = 1.f / sum;
                d_logits[n * 64 + tid]      = e0 * inv;
                d_logits[n * 64 + tid + 32] = e1 * inv;
            }
        }
        gbar();

        // ---------------- phase C: gates + LSTM pointwise ----------------
        if (cta < 128) {
            const int n = cta >> 1, hc2 = cta & 1;
            if (tid < 64) lgs[tid] = __ldcg(&d_logits[n * 64 + tid]);
            __syncthreads();

            const int q2 = tid >> 8, hl = tid & 255;
#pragma unroll
            for (int g2 = 0; g2 < 2; g2++) {
                const int q = q2 * 2 + g2;
                const int j = q * 512 + hc2 * 256 + hl;
                float acc = b_ih[j] + b_hh[j] + pre_t[n * 2048 + j];
#pragma unroll
                for (int s = 0; s < 4; s++)
                    acc += __ldcg(&d_P3[(size_t)(s * 64 + n) * 2048 + j]);
                const uint4* g4 = (const uint4*)&d_G[((size_t)n * 2048 + j) * 64];
#pragma unroll
                for (int pi = 0; pi < 8; pi++) {
                    uint4 u = g4[pi];
                    __half2 h0 = *(__half2*)&u.x, h1 = *(__half2*)&u.y;
                    __half2 h2 = *(__half2*)&u.z, h3 = *(__half2*)&u.w;
                    float2 f0 = __half22float2(h0), f1 = __half22float2(h1);
                    float2 f2 = __half22float2(h2), f3 = __half22float2(h3);
                    const float* w = &lgs[pi * 8];
                    acc += w[0] * f0.x + w[1] * f0.y + w[2] * f1.x + w[3] * f1.y
                         + w[4] * f2.x + w[5] * f2.y + w[6] * f3.x + w[7] * f3.y;
                }
                sg[q * 256 + hl] = acc;
            }
            __syncthreads();

            if (tid < 256) {
                const int hidx = hc2 * 256 + tid;
                float ig = sg[0 * 256 + tid], fg = sg[1 * 256 + tid];
                float gg = sg[2 * 256 + tid], og = sg[3 * 256 + tid];
                float si = 1.f / (1.f + expf(-ig));
                float sf = 1.f / (1.f + expf(-fg));
                float so = 1.f / (1.f + expf(-og));
                float cn = sf * d_c[n * 512 + hidx] + si * tanhf(gg);
                float hn = so * tanhf(cn);
                d_c[n * 512 + hidx] = cn;
                d_h[n * 512 + hidx] = hn;
                size_t o = ((size_t)n * TSTEPS + t) * 512 + hidx;
                __nv_bfloat16 hi = __float2bfloat16(hn);
                d_houtbf_h[o] = hi;
                d_houtbf_l[o] = __float2bfloat16(hn - __bfloat162float(hi));
            }
        }
        gbar();
    }
}

// =====================================================================
// Host side
// =====================================================================
template <typename Tp>
static void* symaddr(Tp& ref)
{
    void* p = nullptr;
    cudaGetSymbolAddress(&p, ref);
    return p;
}

extern "C" void kernel_launch(void* const* d_in, const int* in_sizes, int n_in,
                              void* d_out, int out_size)
{
    const float* features     = (const float*)d_in[0];
    const int*   captions     = (const int*)  d_in[1];
    const float* embd_W       = (const float*)d_in[2];
    const float* attn_token_W = (const float*)d_in[3];
    const float* attn_token_b = (const float*)d_in[4];
    const float* attn_feat_W  = (const float*)d_in[5];
    const float* attn_feat_b  = (const float*)d_in[6];
    const float* attn_full_W  = (const float*)d_in[7];
    // d_in[8] attn_full_b: softmax-invariant constant -> skipped
    const float* W_ih         = (const float*)d_in[9];
    const float* b_ih         = (const float*)d_in[10];
    const float* W_hh         = (const float*)d_in[11];
    const float* b_hh         = (const float*)d_in[12];
    const float* fc_W         = (const float*)d_in[13];
    const float* fc_b         = (const float*)d_in[14];
    const float* init_Wh      = (const float*)d_in[15];
    const float* init_Wc      = (const float*)d_in[16];
    float* out = (float*)d_out;

    __nv_bfloat16* p_feat_h = (__nv_bfloat16*)symaddr(d_feat_h);
    __nv_bfloat16* p_feat_l = (__nv_bfloat16*)symaddr(d_feat_l);
    __nv_bfloat16* p_Wih_h  = (__nv_bfloat16*)symaddr(d_Wih_h);
    __nv_bfloat16* p_Wih_l  = (__nv_bfloat16*)symaddr(d_Wih_l);
    __nv_bfloat16* p_afW_h  = (__nv_bfloat16*)symaddr(d_afW_h);
    __nv_bfloat16* p_afW_l  = (__nv_bfloat16*)symaddr(d_afW_l);
    __nv_bfloat16* p_fcW_h  = (__nv_bfloat16*)symaddr(d_fcW_h);
    __nv_bfloat16* p_fcW_l  = (__nv_bfloat16*)symaddr(d_fcW_l);
    __nv_bfloat16* p_emb_h  = (__nv_bfloat16*)symaddr(d_embbf_h);
    __nv_bfloat16* p_emb_l  = (__nv_bfloat16*)symaddr(d_embbf_l);
    __nv_bfloat16* p_hbf_h  = (__nv_bfloat16*)symaddr(d_houtbf_h);
    __nv_bfloat16* p_hbf_l  = (__nv_bfloat16*)symaddr(d_houtbf_l);

    float* p_pre  = (float*)symaddr(d_pre);
    float* p_part = (float*)symaddr(d_part);
    float* p_h    = (float*)symaddr(d_h);
    float* p_c    = (float*)symaddr(d_c);

    // opt-in to >48KB dynamic smem (idempotent)
    cudaFuncAttributes fa;
    cudaFuncGetAttributes(&fa, mma_nt);
    if (fa.maxDynamicSharedSizeBytes < MMA_SMEM_BYTES)
        cudaFuncSetAttribute(mma_nt, cudaFuncAttributeMaxDynamicSharedMemorySize,
                             MMA_SMEM_BYTES);
    cudaFuncGetAttributes(&fa, init_mma);
    if (fa.maxDynamicSharedSizeBytes < INIT_SMEM_BYTES)
        cudaFuncSetAttribute(init_mma, cudaFuncAttributeMaxDynamicSharedMemorySize,
                             INIT_SMEM_BYTES);
    cudaFuncGetAttributes(&fa, loop_persistent);
    if (fa.maxDynamicSharedSizeBytes < LOOP_SMEM)
        cudaFuncSetAttribute(loop_persistent, cudaFuncAttributeMaxDynamicSharedMemorySize,
                             LOOP_SMEM);

    // side stream + events for prologue fork
    static cudaStream_t s2 = nullptr;
    static cudaEvent_t evA = nullptr, evB = nullptr;
    if (!s2) {
        cudaStreamCreateWithFlags(&s2, cudaStreamNonBlocking);
        cudaEventCreateWithFlags(&evA, cudaEventDisableTiming);
        cudaEventCreateWithFlags(&evB, cudaEventDisableTiming);
    }

    // ---- conversions (stream 0) ----
    cvt_all<<<16032, 256>>>(features, W_ih, attn_feat_W, fc_W);
    cudaEventRecord(evA, 0);

    // ---- fork: init GEMM chain on s2 ----
    cudaStreamWaitEvent(s2, evA, 0);
    init_mma<<<dim3(8, NSPLIT), 256, INIT_SMEM_BYTES, s2>>>(init_Wh, init_Wc, p_part);
    reduce_init<<<256, 256, 0, s2>>>(p_part, p_h, p_c);
    cudaEventRecord(evB, s2);

    // ---- stream 0: remaining prologue ----
    emb_gather_bf<<<TSTEPS * NBATCH, 128>>>(captions, embd_W, p_emb_h, p_emb_l);
    reset_bar<<<1, 1>>>();
    // pre_emb = emb @ W_ih[:,1536:]^T  (2048 x 2048, K=512)
    mma_nt<<<dim3(32, 16, 1), 256, MMA_SMEM_BYTES>>>(
        p_emb_h, p_emb_l, EMBD, TSTEPS * NBATCH, p_Wih_h + 1536, p_Wih_l + 1536, G4,
        p_pre, G4, G4, 8, nullptr, 0);
    // merged: attn_img (fp16) + G (fp16)
    mma_nt<<<dim3(40, 32, 1), 256, MMA_SMEM_BYTES>>>(
        p_feat_h, p_feat_l, ENCC, MROWS, p_afW_h, p_afW_l, ENCC,
        nullptr, ADIM, ADIM, 24, attn_feat_b, 3);

    // ---- join: h0/c0 ready before the recurrence ----
    cudaStreamWaitEvent((cudaStream_t)0, evB, 0);

    // ---- sequential recurrence: ONE persistent kernel ----
    loop_persistent<<<PGRID, 512, LOOP_SMEM>>>(
        attn_token_W, W_hh, attn_token_b, attn_full_W, b_ih, b_hh);

    // ---- epilogue: FC over all timesteps ----
    mma_nt<<<dim3(157, 16, 1), 256, MMA_SMEM_BYTES>>>(
        p_hbf_h, p_hbf_l, HDIM, TSTEPS * NBATCH, p_fcW_h, p_fcW_l, HDIM,
        out, VOCAB, VOCAB, 8, fc_b, 0);
}

// round 11
// speedup vs baseline: 1.2277x; 1.2277x over previous
#include <cuda_runtime.h>
#include <cuda_bf16.h>
#include <cuda_fp16.h>
#include <cstdint>
#include <math.h>

// ---------------- problem constants ----------------
#define TSTEPS 32
#define NBATCH 64
#define NPIX   64
#define ENCC   1536
#define EMBD   512
#define ADIM   512
#define HDIM   512
#define G4     2048     // 4*H
#define VOCAB  10000
#define VPAD   10048    // 157*64
#define MROWS  4096     // N*P
#define KINIT  98304    // P*ENC
#define NSPLIT 96       // init split-K

// ---------------- scratch (__device__ globals; no allocation) ----------------
__device__ __align__(16) __nv_bfloat16 d_feat_h[MROWS * ENCC];
__device__ __align__(16) __nv_bfloat16 d_feat_l[MROWS * ENCC];
__device__ __align__(16) __nv_bfloat16 d_Wih_h[G4 * G4];
__device__ __align__(16) __nv_bfloat16 d_Wih_l[G4 * G4];
__device__ __align__(16) __nv_bfloat16 d_afW_h[ADIM * ENCC];
__device__ __align__(16) __nv_bfloat16 d_afW_l[ADIM * ENCC];
__device__ __align__(16) __nv_bfloat16 d_fcW_h[VPAD * HDIM];
__device__ __align__(16) __nv_bfloat16 d_fcW_l[VPAD * HDIM];
__device__ __align__(16) __nv_bfloat16 d_embbf_h[TSTEPS * NBATCH * EMBD];
__device__ __align__(16) __nv_bfloat16 d_embbf_l[TSTEPS * NBATCH * EMBD];
__device__ __align__(16) __nv_bfloat16 d_houtbf_h[TSTEPS * NBATCH * HDIM];
__device__ __align__(16) __nv_bfloat16 d_houtbf_l[TSTEPS * NBATCH * HDIM];
// stacked small-GEMM weights: rows 0-511 attn_token_W, rows 512-2559 W_hh
__device__ __align__(16) __nv_bfloat16 d_sW_h[2560 * 512];
__device__ __align__(16) __nv_bfloat16 d_sW_l[2560 * 512];
// per-step h in bf16 hi/lo (input to small_mma)
__device__ __align__(16) __nv_bfloat16 d_hbf_h[NBATCH * HDIM];
__device__ __align__(16) __nv_bfloat16 d_hbf_l[NBATCH * HDIM];

__device__ __align__(16) __half d_attn_img[MROWS * ADIM];            // fp16, 4 MB
__device__ __align__(16) __half d_G[(size_t)NBATCH * G4 * NPIX];     // fp16, 16.7 MB
__device__ float d_pre[TSTEPS * NBATCH * G4];
__device__ float d_part[NSPLIT * 64 * 1024];       // init split-K partials (25MB)
__device__ float d_c[NBATCH * HDIM];
__device__ float d_P1[4 * NBATCH * ADIM];
__device__ float d_P3[4 * NBATCH * G4];
__device__ float d_logits[NBATCH * NPIX];

// =====================================================================
// warp-MMA + cp.async helpers (sm_80+ PTX, no arch-feature gating)
// =====================================================================
__device__ __forceinline__ uint32_t smem_u32(const void* p) {
    uint32_t a;
    asm("{ .reg .u64 t; cvta.to.shared.u64 t, %1; cvt.u32.u64 %0, t; }" : "=r"(a) : "l"(p));
    return a;
}
__device__ __forceinline__ void ldsm_x4(uint32_t* r, uint32_t addr) {
    asm volatile("ldmatrix.sync.aligned.m8n8.x4.shared.b16 {%0,%1,%2,%3}, [%4];"
                 : "=r"(r[0]), "=r"(r[1]), "=r"(r[2]), "=r"(r[3]) : "r"(addr));
}
__device__ __forceinline__ void ldsm_x4_t(uint32_t* r, uint32_t addr) {
    asm volatile("ldmatrix.sync.aligned.m8n8.x4.trans.shared.b16 {%0,%1,%2,%3}, [%4];"
                 : "=r"(r[0]), "=r"(r[1]), "=r"(r[2]), "=r"(r[3]) : "r"(addr));
}
__device__ __forceinline__ void mma_bf16(float* c, const uint32_t* a, const uint32_t* b) {
    asm volatile(
        "mma.sync.aligned.m16n8k16.row.col.f32.bf16.bf16.f32 "
        "{%0,%1,%2,%3}, {%4,%5,%6,%7}, {%8,%9}, {%0,%1,%2,%3};"
        : "+f"(c[0]), "+f"(c[1]), "+f"(c[2]), "+f"(c[3])
        : "r"(a[0]), "r"(a[1]), "r"(a[2]), "r"(a[3]), "r"(b[0]), "r"(b[1]));
}
__device__ __forceinline__ void cp16(uint32_t dst, const void* src, bool pred) {
    int sz = pred ? 16 : 0;
    asm volatile("cp.async.cg.shared.global [%0], [%1], 16, %2;"
                 :: "r"(dst), "l"(src), "r"(sz) : "memory");
}
#define CP_COMMIT() asm volatile("cp.async.commit_group;" ::: "memory")
#define CP_WAIT1()  asm volatile("cp.async.wait_group 1;" ::: "memory")

// =====================================================================
// Fused fp32 -> bf16 hi/lo conversion (6 segments).
// blocks: feat 6144 | Wih 4096 | afW 768 | fcW 5024 | tokW 256 | Whh 1024
// =====================================================================
__global__ void cvt_all(const float* __restrict__ feat,
                        const float* __restrict__ Wih,
                        const float* __restrict__ afW,
                        const float* __restrict__ fcW,
                        const float* __restrict__ tokW,
                        const float* __restrict__ Whh)
{
    int b = blockIdx.x;
    const float* src;
    __nv_bfloat16 *dh, *dl;
    int n_src, lb;
    if (b < 6144)       { src = feat; dh = d_feat_h; dl = d_feat_l; n_src = MROWS * ENCC; lb = b; }
    else if (b < 10240) { src = Wih;  dh = d_Wih_h;  dl = d_Wih_l;  n_src = G4 * G4;      lb = b - 6144; }
    else if (b < 11008) { src = afW;  dh = d_afW_h;  dl = d_afW_l;  n_src = ADIM * ENCC;  lb = b - 10240; }
    else if (b < 16032) { src = fcW;  dh = d_fcW_h;  dl = d_fcW_l;  n_src = VOCAB * HDIM; lb = b - 11008; }
    else if (b < 16288) { src = tokW; dh = d_sW_h;   dl = d_sW_l;   n_src = 512 * 512;    lb = b - 16032; }
    else                { src = Whh;  dh = d_sW_h + 262144; dl = d_sW_l + 262144;
                          n_src = 2048 * 512; lb = b - 16288; }
    int i = (lb * 256 + threadIdx.x) * 4;
    float4 v = make_float4(0.f, 0.f, 0.f, 0.f);
    if (i < n_src) v = *(const float4*)&src[i];
    float a[4] = {v.x, v.y, v.z, v.w};
    __nv_bfloat16 h[4], l[4];
#pragma unroll
    for (int j = 0; j < 4; j++) {
        h[j] = __float2bfloat16(a[j]);
        l[j] = __float2bfloat16(a[j] - __bfloat162float(h[j]));
    }
    *(__nv_bfloat162*)&dh[i]     = __halves2bfloat162(h[0], h[1]);
    *(__nv_bfloat162*)&dh[i + 2] = __halves2bfloat162(h[2], h[3]);
    *(__nv_bfloat162*)&dl[i]     = __halves2bfloat162(l[0], l[1]);
    *(__nv_bfloat162*)&dl[i + 2] = __halves2bfloat162(l[2], l[3]);
}

// embedding gather straight into bf16 hi/lo [t*64+n][e]
__global__ void emb_gather_bf(const int* __restrict__ cap,
                              const float* __restrict__ EW,
                              __nv_bfloat16* __restrict__ dh,
                              __nv_bfloat16* __restrict__ dl)
{
    int m = blockIdx.x;                 // t*64+n
    int n = m & 63, t = m >> 6;
    int tok = cap[n * TSTEPS + t];
    int i = threadIdx.x * 4;            // 128 thr * 4 = 512
    float4 v = *(const float4*)&EW[(size_t)tok * EMBD + i];
    float a[4] = {v.x, v.y, v.z, v.w};
    __nv_bfloat16 h[4], l[4];
#pragma unroll
    for (int j = 0; j < 4; j++) {
        h[j] = __float2bfloat16(a[j]);
        l[j] = __float2bfloat16(a[j] - __bfloat162float(h[j]));
    }
    size_t o = (size_t)m * EMBD + i;
    *(__nv_bfloat162*)&dh[o]     = __halves2bfloat162(h[0], h[1]);
    *(__nv_bfloat162*)&dh[o + 2] = __halves2bfloat162(h[2], h[3]);
    *(__nv_bfloat162*)&dl[o]     = __halves2bfloat162(l[0], l[1]);
    *(__nv_bfloat162*)&dl[o + 2] = __halves2bfloat162(l[2], l[3]);
}

// =====================================================================
// Warp-MMA NT GEMM, bf16 hi/lo split, fp32 accumulate, cp.async 2-stage.
// mode 0: fp32 C[m*ldc+n] (+bias)
// mode 3: merged — blockIdx.x<8: attn_img fp16 (+bias); else G fp16 layout
// =====================================================================
#define ASTR 72
#define AH_OFF 0
#define AL_OFF 18432
#define BH_OFF 36864
#define BL_OFF 46080
#define STAGE_BYTES 55296
#define MMA_SMEM_BYTES (2 * STAGE_BYTES)

__global__ void __launch_bounds__(256) mma_nt(
    const __nv_bfloat16* __restrict__ Ah, const __nv_bfloat16* __restrict__ Al,
    int lda, int Mvalid,
    const __nv_bfloat16* __restrict__ Bh, const __nv_bfloat16* __restrict__ Bl,
    int ldb,
    float* __restrict__ C, int Nvalid, int ldc,
    int chunks, const float* __restrict__ bias, int mode)
{
    extern __shared__ char smem[];
    const uint32_t sb = smem_u32(smem);
    const int tid = threadIdx.x, lane = tid & 31, wid = tid >> 5;
    const int wm = wid >> 1, wn = wid & 1;
    const int m0 = blockIdx.y * 128;

    const __nv_bfloat16* bH = Bh;
    const __nv_bfloat16* bL = Bl;
    const float* bptr = bias;
    int n0 = blockIdx.x * 64;
    int mode_eff = mode;
    if (mode == 3) {
        if (blockIdx.x < 8) {
            mode_eff = 4;                       // attn_img fp16 store
        } else {
            bH = d_Wih_h; bL = d_Wih_l; ldb = G4;
            bptr = nullptr;
            n0 = (blockIdx.x - 8) * 64;
            mode_eff = 1;                       // G fp16 store
        }
    }

    float acc[2][4][4];
#pragma unroll
    for (int i = 0; i < 2; i++)
#pragma unroll
        for (int j = 0; j < 4; j++)
#pragma unroll
            for (int q = 0; q < 4; q++) acc[i][j][q] = 0.f;

    const uint32_t a_row = wm * 32 + (lane & 15);
    const uint32_t a_k   = ((lane >> 4) & 1) * 8;
    const uint32_t b_row = wn * 32 + (lane & 7) + ((lane >> 4) & 1) * 8;
    const uint32_t b_k   = ((lane >> 3) & 1) * 8;

    auto load_stage = [&](int ic, int st) {
        const uint32_t stb = sb + st * STAGE_BYTES;
        const long long kc = (long long)ic * 64;
#pragma unroll
        for (int it = 0; it < 4; it++) {              // A: 128 rows x 64k
            int idx = it * 256 + tid;
            int row = idx >> 3, k8 = (idx & 7) * 8;
            int m = m0 + row;
            bool p = (m < Mvalid);
            int mc = p ? m : (Mvalid - 1);
            uint32_t off = (row * ASTR + k8) * 2;
            cp16(stb + AH_OFF + off, &Ah[(size_t)mc * lda + kc + k8], p);
            cp16(stb + AL_OFF + off, &Al[(size_t)mc * lda + kc + k8], p);
        }
#pragma unroll
        for (int it = 0; it < 2; it++) {              // B: 64 rows x 64k
            int idx = it * 256 + tid;
            int row = idx >> 3, k8 = (idx & 7) * 8;
            uint32_t off = (row * ASTR + k8) * 2;
            cp16(stb + BH_OFF + off, &bH[(size_t)(n0 + row) * ldb + kc + k8], true);
            cp16(stb + BL_OFF + off, &bL[(size_t)(n0 + row) * ldb + kc + k8], true);
        }
    };

    load_stage(0, 0);
    CP_COMMIT();

    for (int ic = 0; ic < chunks; ic++) {
        const int s = ic & 1;
        if (ic + 1 < chunks) load_stage(ic + 1, s ^ 1);
        CP_COMMIT();
        CP_WAIT1();
        __syncthreads();

        const uint32_t stb = sb + s * STAGE_BYTES;
#pragma unroll
        for (int ks = 0; ks < 4; ks++) {
            const uint32_t k16 = ks * 16;
            uint32_t ahf[2][4], alf[2][4], bhf[2][4], blf[2][4];
#pragma unroll
            for (int mt = 0; mt < 2; mt++) {
                uint32_t off = ((a_row + mt * 16) * ASTR + k16 + a_k) * 2;
                ldsm_x4(ahf[mt], stb + AH_OFF + off);
                ldsm_x4(alf[mt], stb + AL_OFF + off);
            }
#pragma unroll
            for (int np = 0; np < 2; np++) {
                uint32_t off = ((b_row + np * 16) * ASTR + k16 + b_k) * 2;
                ldsm_x4(bhf[np], stb + BH_OFF + off);
                ldsm_x4(blf[np], stb + BL_OFF + off);
            }
#pragma unroll
            for (int mt = 0; mt < 2; mt++)
#pragma unroll
                for (int np = 0; np < 2; np++) {
                    mma_bf16(acc[mt][np * 2 + 0], ahf[mt], &bhf[np][0]);
                    mma_bf16(acc[mt][np * 2 + 1], ahf[mt], &bhf[np][2]);
                    mma_bf16(acc[mt][np * 2 + 0], ahf[mt], &blf[np][0]);
                    mma_bf16(acc[mt][np * 2 + 1], ahf[mt], &blf[np][2]);
                    mma_bf16(acc[mt][np * 2 + 0], alf[mt], &bhf[np][0]);
                    mma_bf16(acc[mt][np * 2 + 1], alf[mt], &bhf[np][2]);
                }
        }
        __syncthreads();
    }

    // ---- store ----
    const int g = lane >> 2, tg = lane & 3;
#pragma unroll
    for (int mt = 0; mt < 2; mt++) {
#pragma unroll
        for (int nt = 0; nt < 4; nt++) {
            int r0 = m0 + wm * 32 + mt * 16 + g;
            int c0 = n0 + wn * 32 + nt * 8 + tg * 2;
#pragma unroll
            for (int q = 0; q < 4; q++) {
                int m = r0 + (q >> 1) * 8;
                int n = c0 + (q & 1);
                if (m >= Mvalid) continue;
                float v = acc[mt][nt][q];
                if (mode_eff == 1) {
                    int nb = m >> 6, p = m & 63;
                    d_G[((size_t)nb * 2048 + n) * 64 + p] = __float2half(v);
                } else if (mode_eff == 4) {
                    d_attn_img[(size_t)m * ADIM + n] = __float2half(v + bptr[n]);
                } else {
                    if (n < Nvalid) {
                        if (bptr) v += bptr[n];
                        C[(size_t)m * ldc + n] = v;
                    }
                }
            }
        }
    }
}

// =====================================================================
// Fused init GEMM: h0|c0 = F(64x98304) @ [Wh|Wc]; split-K 96. (R7/R9)
// =====================================================================
#define IBSTR 136
#define IA_H 0
#define IA_L 9216
#define IB_H 18432
#define IB_L 35840
#define INIT_SMEM_BYTES 53248

__global__ void __launch_bounds__(256) init_mma(
    const float* __restrict__ Wh, const float* __restrict__ Wc,
    float* __restrict__ P)
{
    extern __shared__ char smem[];
    const uint32_t sb = smem_u32(smem);
    __nv_bfloat16* Bsh = (__nv_bfloat16*)(smem + IB_H);
    __nv_bfloat16* Bsl = (__nv_bfloat16*)(smem + IB_L);
    const int tid = threadIdx.x, lane = tid & 31, wid = tid >> 5;
    const int wm = wid >> 2, wn = wid & 3;        // 2 x 4 warps, tile 64m x 128n
    const int bx = blockIdx.x;                    // 0-3 Wh, 4-7 Wc
    const float* __restrict__ W = (bx < 4) ? Wh : Wc;
    const int n0g = (bx & 3) * 128;
    const int outc0 = bx * 128;
    const size_t k0 = (size_t)blockIdx.y * 1024;

    float acc[2][4][4];
#pragma unroll
    for (int i = 0; i < 2; i++)
#pragma unroll
        for (int j = 0; j < 4; j++)
#pragma unroll
            for (int q = 0; q < 4; q++) acc[i][j][q] = 0.f;

    const uint32_t a_row = wm * 32 + (lane & 15);
    const uint32_t a_k   = ((lane >> 4) & 1) * 8;
    const uint32_t bt_k = ((lane >> 3) & 1) * 8 + (lane & 7);
    const uint32_t bt_n = ((lane >> 4) & 1) * 8;

    for (int ic = 0; ic < 16; ic++) {
        const size_t kg = k0 + ic * 64;
#pragma unroll
        for (int it = 0; it < 2; it++) {
            int idx = it * 256 + tid;
            int row = idx >> 3, k8 = (idx & 7) * 8;
            uint32_t off = (row * ASTR + k8) * 2;
            *(uint4*)(smem + IA_H + off) = *(const uint4*)&d_feat_h[(size_t)row * KINIT + kg + k8];
            *(uint4*)(smem + IA_L + off) = *(const uint4*)&d_feat_l[(size_t)row * KINIT + kg + k8];
        }
#pragma unroll
        for (int it = 0; it < 8; it++) {
            int idx = it * 256 + tid;
            int kk = idx >> 5, nn = (idx & 31) * 4;
            float4 v = *(const float4*)&W[(kg + kk) * 512 + n0g + nn];
            float a[4] = {v.x, v.y, v.z, v.w};
            __nv_bfloat16 h[4], l[4];
#pragma unroll
            for (int j = 0; j < 4; j++) {
                h[j] = __float2bfloat16(a[j]);
                l[j] = __float2bfloat16(a[j] - __bfloat162float(h[j]));
            }
            int o = kk * IBSTR + nn;
            *(__nv_bfloat162*)&Bsh[o]     = __halves2bfloat162(h[0], h[1]);
            *(__nv_bfloat162*)&Bsh[o + 2] = __halves2bfloat162(h[2], h[3]);
            *(__nv_bfloat162*)&Bsl[o]     = __halves2bfloat162(l[0], l[1]);
            *(__nv_bfloat162*)&Bsl[o + 2] = __halves2bfloat162(l[2], l[3]);
        }
        __syncthreads();

#pragma unroll
        for (int ks = 0; ks < 4; ks++) {
            const uint32_t k16 = ks * 16;
            uint32_t ahf[2][4], alf[2][4];
#pragma unroll
            for (int mt = 0; mt < 2; mt++) {
                uint32_t off = ((a_row + mt * 16) * ASTR + k16 + a_k) * 2;
                ldsm_x4(ahf[mt], sb + IA_H + off);
                ldsm_x4(alf[mt], sb + IA_L + off);
            }
#pragma unroll
            for (int ng = 0; ng < 2; ng++) {
                uint32_t bhf[4], blf[4];
                uint32_t off = ((k16 + bt_k) * IBSTR + wn * 32 + ng * 16 + bt_n) * 2;
                ldsm_x4_t(bhf, sb + IB_H + off);
                ldsm_x4_t(blf, sb + IB_L + off);
#pragma unroll
                for (int mt = 0; mt < 2; mt++) {
                    mma_bf16(acc[mt][ng * 2 + 0], ahf[mt], &bhf[0]);
                    mma_bf16(acc[mt][ng * 2 + 1], ahf[mt], &bhf[2]);
                    mma_bf16(acc[mt][ng * 2 + 0], ahf[mt], &blf[0]);
                    mma_bf16(acc[mt][ng * 2 + 1], ahf[mt], &blf[2]);
                    mma_bf16(acc[mt][ng * 2 + 0], alf[mt], &bhf[0]);
                    mma_bf16(acc[mt][ng * 2 + 1], alf[mt], &bhf[2]);
                }
            }
        }
        __syncthreads();
    }

    const int g = lane >> 2, tg = lane & 3;
    const int zb = blockIdx.y * 64;
#pragma unroll
    for (int mt = 0; mt < 2; mt++)
#pragma unroll
        for (int nt = 0; nt < 4; nt++) {
            int r0 = wm * 32 + mt * 16 + g;
            int c0 = outc0 + wn * 32 + nt * 8 + tg * 2;
#pragma unroll
            for (int q = 0; q < 4; q++) {
                int m = r0 + (q >> 1) * 8;
                int n = c0 + (q & 1);
                P[(size_t)(zb + m) * 1024 + n] = acc[mt][nt][q];
            }
        }
}

// deterministic reduce of NSPLIT split-K partials -> h0 (bf16 hi/lo), c0
__global__ void reduce_init(const float* __restrict__ P,
                            float* __restrict__ c)
{
    int r = blockIdx.x * 256 + threadIdx.x;   // 65536
    float s = 0.f;
#pragma unroll
    for (int j = 0; j < NSPLIT; j++) s += P[(size_t)j * 65536 + r];
    int m = r >> 10, col = r & 1023;
    if (col < 512) {
        __nv_bfloat16 hi = __float2bfloat16(s);
        d_hbf_h[m * 512 + col] = hi;
        d_hbf_l[m * 512 + col] = __float2bfloat16(s - __bfloat162float(hi));
    } else {
        c[m * 512 + col - 512] = s;
    }
}

// =====================================================================
// Per-step small GEMM on TENSOR CORES: [P1|P3] partials from bf16 hi/lo h.
// A = d_hbf (64 x 512), B = d_sW (2560 x 512, tokW rows 0-511 then W_hh).
// grid (40 cb, 4 ks), 128 threads (2x2 warps), tile 64m x 64n x 128k.
// Partials layout identical to old small_nt2 (consumer kernels unchanged).
// =====================================================================
#define SSTR 136
#define S_AH 0
#define S_AL 17408
#define S_BH 34816
#define S_BL 52224
#define SMALL_SMEM 69632

__global__ void __launch_bounds__(128) small_mma(
    float* __restrict__ P1o, float* __restrict__ P3o)
{
    extern __shared__ char smem[];
    const uint32_t sb = smem_u32(smem);
    const int tid = threadIdx.x, lane = tid & 31, wid = tid >> 5;
    const int wm = wid >> 1, wn = wid & 1;
    const int cb = blockIdx.x, ks = blockIdx.y;
    const int k0 = ks * 128;

    float* __restrict__ P;
    int Ncols, cbl;
    if (cb < 8) { P = P1o; Ncols = 512;  cbl = cb; }
    else        { P = P3o; Ncols = 2048; cbl = cb - 8; }

    // ---- load A (64x128) and B (64x128) hi/lo, K-major ----
#pragma unroll
    for (int it = 0; it < 8; it++) {
        int idx = it * 128 + tid;            // 1024 = 64 rows * 16 uint4
        int row = idx >> 4, c8 = (idx & 15) * 8;
        uint32_t off = (row * SSTR + c8) * 2;
        *(uint4*)(smem + S_AH + off) = *(const uint4*)&d_hbf_h[row * 512 + k0 + c8];
        *(uint4*)(smem + S_AL + off) = *(const uint4*)&d_hbf_l[row * 512 + k0 + c8];
        *(uint4*)(smem + S_BH + off) = *(const uint4*)&d_sW_h[(size_t)(cb * 64 + row) * 512 + k0 + c8];
        *(uint4*)(smem + S_BL + off) = *(const uint4*)&d_sW_l[(size_t)(cb * 64 + row) * 512 + k0 + c8];
    }
    __syncthreads();

    float acc[2][4][4];
#pragma unroll
    for (int i = 0; i < 2; i++)
#pragma unroll
        for (int j = 0; j < 4; j++)
#pragma unroll
            for (int q = 0; q < 4; q++) acc[i][j][q] = 0.f;

    const uint32_t a_row = wm * 32 + (lane & 15);
    const uint32_t a_k   = ((lane >> 4) & 1) * 8;
    const uint32_t b_row = wn * 32 + (lane & 7) + ((lane >> 4) & 1) * 8;
    const uint32_t b_k   = ((lane >> 3) & 1) * 8;

#pragma unroll
    for (int k16i = 0; k16i < 8; k16i++) {
        const uint32_t k16 = k16i * 16;
        uint32_t ahf[2][4], alf[2][4], bhf[2][4], blf[2][4];
#pragma unroll
        for (int mt = 0; mt < 2; mt++) {
            uint32_t off = ((a_row + mt * 16) * SSTR + k16 + a_k) * 2;
            ldsm_x4(ahf[mt], sb + S_AH + off);
            ldsm_x4(alf[mt], sb + S_AL + off);
        }
#pragma unroll
        for (int np = 0; np < 2; np++) {
            uint32_t off = ((b_row + np * 16) * SSTR + k16 + b_k) * 2;
            ldsm_x4(bhf[np], sb + S_BH + off);
            ldsm_x4(blf[np], sb + S_BL + off);
        }
#pragma unroll
        for (int mt = 0; mt < 2; mt++)
#pragma unroll
            for (int np = 0; np < 2; np++) {
                mma_bf16(acc[mt][np * 2 + 0], ahf[mt], &bhf[np][0]);
                mma_bf16(acc[mt][np * 2 + 1], ahf[mt], &bhf[np][2]);
                mma_bf16(acc[mt][np * 2 + 0], ahf[mt], &blf[np][0]);
                mma_bf16(acc[mt][np * 2 + 1], ahf[mt], &blf[np][2]);
                mma_bf16(acc[mt][np * 2 + 0], alf[mt], &bhf[np][0]);
                mma_bf16(acc[mt][np * 2 + 1], alf[mt], &bhf[np][2]);
            }
    }

    // ---- store partials: P[(ks*64 + m)*Ncols + cbl*64 + n] ----
    const int g = lane >> 2, tg = lane & 3;
#pragma unroll
    for (int mt = 0; mt < 2; mt++)
#pragma unroll
        for (int nt = 0; nt < 4; nt++) {
            int r0 = wm * 32 + mt * 16 + g;
            int c0 = cbl * 64 + wn * 32 + nt * 8 + tg * 2;
#pragma unroll
            for (int q = 0; q < 4; q++) {
                int m = r0 + (q >> 1) * 8;
                int n = c0 + (q & 1);
                P[(size_t)(ks * 64 + m) * Ncols + n] = acc[mt][nt][q];
            }
        }
}

// =====================================================================
// Attention scores + softmax (attn_img fp16)
// =====================================================================
__global__ void attn_softmax(const float* __restrict__ P1,
                             const float* __restrict__ tb,
                             const float* __restrict__ wfull)
{
    const int n = blockIdx.x, tid = threadIdx.x;
    __shared__ float ah[512], wf[512], sc[64];
    float v = tb[tid];
#pragma unroll
    for (int s = 0; s < 4; s++) v += P1[(size_t)(s * 64 + n) * 512 + tid];
    ah[tid] = v;
    wf[tid] = wfull[tid];
    __syncthreads();

    const int warp = tid >> 5, lane = tid & 31;
    for (int p = warp; p < 64; p += 16) {
        const __half* img = &d_attn_img[(size_t)(n * 64 + p) * 512];
        float s = 0.f;
#pragma unroll
        for (int a = lane; a < 512; a += 32) {
            float e = ah[a] + __half2float(img[a]);
            if (e > 0.f) s += e * wf[a];
        }
#pragma unroll
        for (int o = 16; o > 0; o >>= 1) s += __shfl_xor_sync(0xFFFFFFFFu, s, o);
        if (lane == 0) sc[p] = s;
    }
    __syncthreads();
    if (tid < 32) {
        float s0 = sc[tid], s1 = sc[tid + 32];
        float mx = fmaxf(s0, s1);
#pragma unroll
        for (int o = 16; o > 0; o >>= 1) mx = fmaxf(mx, __shfl_xor_sync(0xFFFFFFFFu, mx, o));
        float e0 = expf(s0 - mx), e1 = expf(s1 - mx);
        float sum = e0 + e1;
#pragma unroll
        for (int o = 16; o > 0; o >>= 1) sum += __shfl_xor_sync(0xFFFFFFFFu, sum, o);
        float inv = 1.f / sum;
        d_logits[n * 64 + tid]      = e0 * inv;
        d_logits[n * 64 + tid + 32] = e1 * inv;
    }
}

// =====================================================================
// Gates assembly + LSTM pointwise (G fp16); writes h as bf16 hi/lo
// (both d_hbf for next step and d_houtbf for the FC epilogue).
// grid (64 n, 8 hchunk), 256 threads — full-chip G bandwidth.
// =====================================================================
__global__ void gates_lstm(const float* __restrict__ P3,
                           const float* __restrict__ pre_t,
                           const float* __restrict__ b_ih,
                           const float* __restrict__ b_hh,
                           int t)
{
    const int n = blockIdx.x, hc = blockIdx.y, tid = threadIdx.x;
    __shared__ float lg[64];
    __shared__ float sg[4][64];
    if (tid < 64) lg[tid] = d_logits[n * 64 + tid];
    __syncthreads();

    const int q = tid >> 6, hl = tid & 63;
    const int j = q * 512 + hc * 64 + hl;
    float acc = b_ih[j] + b_hh[j] + pre_t[n * 2048 + j];
#pragma unroll
    for (int s = 0; s < 4; s++) acc += P3[(size_t)(s * 64 + n) * 2048 + j];
    const uint4* g4 = (const uint4*)&d_G[((size_t)n * 2048 + j) * 64];
#pragma unroll
    for (int pi = 0; pi < 8; pi++) {
        uint4 u = g4[pi];
        __half2 h0 = *(__half2*)&u.x, h1 = *(__half2*)&u.y;
        __half2 h2 = *(__half2*)&u.z, h3 = *(__half2*)&u.w;
        float2 f0 = __half22float2(h0), f1 = __half22float2(h1);
        float2 f2 = __half22float2(h2), f3 = __half22float2(h3);
        const float* w = &lg[pi * 8];
        acc += w[0] * f0.x + w[1] * f0.y + w[2] * f1.x + w[3] * f1.y
             + w[4] * f2.x + w[5] * f2.y + w[6] * f3.x + w[7] * f3.y;
    }
    sg[q][hl] = acc;
    __syncthreads();

    if (tid < 64) {
        int hidx = hc * 64 + tid;
        float ig = sg[0][tid], fg = sg[1][tid], gg = sg[2][tid], og = sg[3][tid];
        float si = 1.f / (1.f + expf(-ig));
        float sf = 1.f / (1.f + expf(-fg));
        float so = 1.f / (1.f + expf(-og));
        float cn = sf * d_c[n * 512 + hidx] + si * tanhf(gg);
        float hn = so * tanhf(cn);
        d_c[n * 512 + hidx] = cn;
        __nv_bfloat16 hi = __float2bfloat16(hn);
        __nv_bfloat16 lo = __float2bfloat16(hn - __bfloat162float(hi));
        d_hbf_h[n * 512 + hidx] = hi;
        d_hbf_l[n * 512 + hidx] = lo;
        size_t o = ((size_t)n * TSTEPS + t) * 512 + hidx;
        d_houtbf_h[o] = hi;
        d_houtbf_l[o] = lo;
    }
}

// =====================================================================
// Host side
// =====================================================================
template <typename Tp>
static void* symaddr(Tp& ref)
{
    void* p = nullptr;
    cudaGetSymbolAddress(&p, ref);
    return p;
}

extern "C" void kernel_launch(void* const* d_in, const int* in_sizes, int n_in,
                              void* d_out, int out_size)
{
    const float* features     = (const float*)d_in[0];
    const int*   captions     = (const int*)  d_in[1];
    const float* embd_W       = (const float*)d_in[2];
    const float* attn_token_W = (const float*)d_in[3];
    const float* attn_token_b = (const float*)d_in[4];
    const float* attn_feat_W  = (const float*)d_in[5];
    const float* attn_feat_b  = (const float*)d_in[6];
    const float* attn_full_W  = (const float*)d_in[7];
    // d_in[8] attn_full_b: softmax-invariant constant -> skipped
    const float* W_ih         = (const float*)d_in[9];
    const float* b_ih         = (const float*)d_in[10];
    const float* W_hh         = (const float*)d_in[11];
    const float* b_hh         = (const float*)d_in[12];
    const float* fc_W         = (const float*)d_in[13];
    const float* fc_b         = (const float*)d_in[14];
    const float* init_Wh      = (const float*)d_in[15];
    const float* init_Wc      = (const float*)d_in[16];
    float* out = (float*)d_out;

    __nv_bfloat16* p_feat_h = (__nv_bfloat16*)symaddr(d_feat_h);
    __nv_bfloat16* p_feat_l = (__nv_bfloat16*)symaddr(d_feat_l);
    __nv_bfloat16* p_Wih_h  = (__nv_bfloat16*)symaddr(d_Wih_h);
    __nv_bfloat16* p_Wih_l  = (__nv_bfloat16*)symaddr(d_Wih_l);
    __nv_bfloat16* p_afW_h  = (__nv_bfloat16*)symaddr(d_afW_h);
    __nv_bfloat16* p_afW_l  = (__nv_bfloat16*)symaddr(d_afW_l);
    __nv_bfloat16* p_fcW_h  = (__nv_bfloat16*)symaddr(d_fcW_h);
    __nv_bfloat16* p_fcW_l  = (__nv_bfloat16*)symaddr(d_fcW_l);
    __nv_bfloat16* p_emb_h  = (__nv_bfloat16*)symaddr(d_embbf_h);
    __nv_bfloat16* p_emb_l  = (__nv_bfloat16*)symaddr(d_embbf_l);
    __nv_bfloat16* p_hbf_h  = (__nv_bfloat16*)symaddr(d_houtbf_h);
    __nv_bfloat16* p_hbf_l  = (__nv_bfloat16*)symaddr(d_houtbf_l);

    float* p_pre  = (float*)symaddr(d_pre);
    float* p_part = (float*)symaddr(d_part);
    float* p_c    = (float*)symaddr(d_c);
    float* p_P1   = (float*)symaddr(d_P1);
    float* p_P3   = (float*)symaddr(d_P3);

    // opt-in to >48KB dynamic smem (idempotent)
    cudaFuncAttributes fa;
    cudaFuncGetAttributes(&fa, mma_nt);
    if (fa.maxDynamicSharedSizeBytes < MMA_SMEM_BYTES)
        cudaFuncSetAttribute(mma_nt, cudaFuncAttributeMaxDynamicSharedMemorySize,
                             MMA_SMEM_BYTES);
    cudaFuncGetAttributes(&fa, init_mma);
    if (fa.maxDynamicSharedSizeBytes < INIT_SMEM_BYTES)
        cudaFuncSetAttribute(init_mma, cudaFuncAttributeMaxDynamicSharedMemorySize,
                             INIT_SMEM_BYTES);
    cudaFuncGetAttributes(&fa, small_mma);
    if (fa.maxDynamicSharedSizeBytes < SMALL_SMEM)
        cudaFuncSetAttribute(small_mma, cudaFuncAttributeMaxDynamicSharedMemorySize,
                             SMALL_SMEM);

    // side stream + events for prologue fork
    static cudaStream_t s2 = nullptr;
    static cudaEvent_t evA = nullptr, evB = nullptr;
    if (!s2) {
        cudaStreamCreateWithFlags(&s2, cudaStreamNonBlocking);
        cudaEventCreateWithFlags(&evA, cudaEventDisableTiming);
        cudaEventCreateWithFlags(&evB, cudaEventDisableTiming);
    }

    // ---- conversions (stream 0) ----
    cvt_all<<<17312, 256>>>(features, W_ih, attn_feat_W, fc_W,
                            attn_token_W, W_hh);
    cudaEventRecord(evA, 0);

    // ---- fork: init GEMM chain on s2 ----
    cudaStreamWaitEvent(s2, evA, 0);
    init_mma<<<dim3(8, NSPLIT), 256, INIT_SMEM_BYTES, s2>>>(init_Wh, init_Wc, p_part);
    reduce_init<<<256, 256, 0, s2>>>(p_part, p_c);
    cudaEventRecord(evB, s2);

    // ---- stream 0: remaining prologue ----
    emb_gather_bf<<<TSTEPS * NBATCH, 128>>>(captions, embd_W, p_emb_h, p_emb_l);
    // pre_emb = emb @ W_ih[:,1536:]^T  (2048 x 2048, K=512)
    mma_nt<<<dim3(32, 16, 1), 256, MMA_SMEM_BYTES>>>(
        p_emb_h, p_emb_l, EMBD, TSTEPS * NBATCH, p_Wih_h + 1536, p_Wih_l + 1536, G4,
        p_pre, G4, G4, 8, nullptr, 0);
    // merged: attn_img (fp16) + G (fp16)
    mma_nt<<<dim3(40, 32, 1), 256, MMA_SMEM_BYTES>>>(
        p_feat_h, p_feat_l, ENCC, MROWS, p_afW_h, p_afW_l, ENCC,
        nullptr, ADIM, ADIM, 24, attn_feat_b, 3);

    // ---- join: h0/c0 ready before the recurrence ----
    cudaStreamWaitEvent((cudaStream_t)0, evB, 0);

    // ---- sequential recurrence (3 launches/step; h-GEMMs on tensor cores) ----
    for (int t = 0; t < TSTEPS; ++t) {
        small_mma<<<dim3(40, 4), 128, SMALL_SMEM>>>(p_P1, p_P3);
        attn_softmax<<<64, 512>>>(p_P1, attn_token_b, attn_full_W);
        gates_lstm<<<dim3(64, 8), 256>>>(p_P3, p_pre + (size_t)t * NBATCH * G4,
                                         b_ih, b_hh, t);
    }

    // ---- epilogue: FC over all timesteps ----
    mma_nt<<<dim3(157, 16, 1), 256, MMA_SMEM_BYTES>>>(
        p_hbf_h, p_hbf_l, HDIM, TSTEPS * NBATCH, p_fcW_h, p_fcW_l, HDIM,
        out, VOCAB, VOCAB, 8, fc_b, 0);
}